// round 13
// baseline (speedup 1.0000x reference)
#include <cuda_runtime.h>
#include <cuda_bf16.h>
#include <cstdint>
#include <math.h>

// Problem dims
#define Bb   8
#define Nn   2048
#define Ee   8192
#define Tt   4096
#define HH   128
#define CD   1024   // B*HH

// ---------------------------------------------------------------------------
// Scratch (static device globals). NEVER pass these as kernel arguments from
// host code (host shadow symbol + GB300 ATS silently writes host memory —
// the R8/R9 bug). All bindings happen inside device code.
// ---------------------------------------------------------------------------
__device__ __nv_bfloat16 g_B1T_hi[(size_t)Ee * Nn];      // B1^T  [E,N]
__device__ __nv_bfloat16 g_B1T_lo[(size_t)Ee * Nn];
__device__ __nv_bfloat16 g_B1_hi [(size_t)Nn * Ee];      // B1    [N,E]
__device__ __nv_bfloat16 g_B1_lo [(size_t)Nn * Ee];
__device__ __nv_bfloat16 g_HT_hi [(size_t)Bb * HH * Nn]; // H^T [b][h][n]
__device__ __nv_bfloat16 g_HT_lo [(size_t)Bb * HH * Nn];
__device__ __nv_bfloat16 g_EtT_hi[(size_t)CD * Ee];      // Etopo^T [b*128+h][e]
__device__ __nv_bfloat16 g_EtT_lo[(size_t)CD * Ee];
__device__ float g_dH[(size_t)2 * Bb * Nn * HH];         // 2 K-split partials
__device__ float g_L1[Ee];
__device__ float g_L1part[64][Ee];

// ---------------------------------------------------------------------------
// Base-ISA helpers (sm_80 features only — plain compute_103 safe)
// ---------------------------------------------------------------------------
__device__ __forceinline__ uint32_t smem_to_u32(const void* p) {
    uint32_t a;
    asm("{ .reg .u64 t; cvta.to.shared.u64 t, %1; cvt.u32.u64 %0, t; }"
        : "=r"(a) : "l"(p));
    return a;
}
#define CP_COMMIT() asm volatile("cp.async.commit_group;" ::: "memory")
#define CP_WAIT(n)  asm volatile("cp.async.wait_group %0;" :: "n"(n) : "memory")

__device__ __forceinline__ void cp_async16(uint32_t dst, const void* src) {
    asm volatile("cp.async.cg.shared.global [%0], [%1], 16;" :: "r"(dst), "l"(src));
}
__device__ __forceinline__ void ldsm_x4(uint32_t& r0, uint32_t& r1,
                                        uint32_t& r2, uint32_t& r3, uint32_t a) {
    asm volatile("ldmatrix.sync.aligned.m8n8.x4.shared.b16 {%0,%1,%2,%3}, [%4];"
                 : "=r"(r0), "=r"(r1), "=r"(r2), "=r"(r3) : "r"(a));
}
__device__ __forceinline__ void mma_bf16(float d[4], const uint32_t a[4],
                                         const uint32_t b[2]) {
    asm volatile(
        "mma.sync.aligned.m16n8k16.row.col.f32.bf16.bf16.f32 "
        "{%0,%1,%2,%3}, {%4,%5,%6,%7}, {%8,%9}, {%0,%1,%2,%3};"
        : "+f"(d[0]), "+f"(d[1]), "+f"(d[2]), "+f"(d[3])
        : "r"(a[0]), "r"(a[1]), "r"(a[2]), "r"(a[3]), "r"(b[0]), "r"(b[1]));
}
__device__ __forceinline__ void bf16_split(float a, __nv_bfloat16& h, __nv_bfloat16& l) {
    h = __float2bfloat16(a);
    l = __float2bfloat16(a - __bfloat162float(h));
}

// ---------------------------------------------------------------------------
// Prep kernels. tsplit = 32x32 transpose + bf16 hi/lo split.
// ---------------------------------------------------------------------------
__device__ __forceinline__ void tsplit_body(
    const float* __restrict__ in, int ld_in,
    __nv_bfloat16* __restrict__ hi, __nv_bfloat16* __restrict__ lo,
    int ld_out) {
    __shared__ float t[32][33];
    const int r0 = blockIdx.y * 32, c0 = blockIdx.x * 32;
    const int x = threadIdx.x, y = threadIdx.y;
#pragma unroll
    for (int i = 0; i < 32; i += 8)
        t[y + i][x] = in[(size_t)(r0 + y + i) * ld_in + c0 + x];
    __syncthreads();
#pragma unroll
    for (int i = 0; i < 32; i += 8) {
        float v = t[x][y + i];
        __nv_bfloat16 h, l;
        bf16_split(v, h, l);
        size_t o = (size_t)(c0 + y + i) * ld_out + r0 + x;
        hi[o] = h; lo[o] = l;
    }
}

// B1 [N,E]: emits B1T hi/lo [E,N] (transposed), B1 hi/lo [N,E] (straight),
// and per-32-row-block L1 partial sums. One read of B1.
__global__ void tsplit_b1_kernel(const float* __restrict__ B1) {
    __shared__ float t[32][33];
    __shared__ float ps[8][32];
    const int r0 = blockIdx.y * 32, c0 = blockIdx.x * 32;
    const int x = threadIdx.x, y = threadIdx.y;
    float s = 0.f;
#pragma unroll
    for (int i = 0; i < 32; i += 8) {
        float v = B1[(size_t)(r0 + y + i) * Ee + c0 + x];
        t[y + i][x] = v;
        s += v * v;
        __nv_bfloat16 h, l;
        bf16_split(v, h, l);
        const size_t o = (size_t)(r0 + y + i) * Ee + c0 + x;
        g_B1_hi[o] = h; g_B1_lo[o] = l;
    }
    ps[y][x] = s;
    __syncthreads();
    if (y == 0) {
        float tot = 0.f;
#pragma unroll
        for (int k = 0; k < 8; k++) tot += ps[k][x];
        g_L1part[blockIdx.y][c0 + x] = tot;
    }
#pragma unroll
    for (int i = 0; i < 32; i += 8) {
        float v = t[x][y + i];
        __nv_bfloat16 h, l;
        bf16_split(v, h, l);
        size_t o = (size_t)(c0 + y + i) * Nn + r0 + x;
        g_B1T_hi[o] = h; g_B1T_lo[o] = l;
    }
}

// H [b][n][h] -> g_HT hi/lo [b][h][n]
__global__ void tsplit_h_kernel(const float* __restrict__ H) {
    const size_t ib = (size_t)blockIdx.z * (Nn * HH);
    const size_t ob = (size_t)blockIdx.z * (HH * Nn);
    tsplit_body(H + ib, HH, g_HT_hi + ob, g_HT_lo + ob, Nn);
}

__global__ void l1_finalize_kernel(const float* __restrict__ B2) {
    const int warp = threadIdx.x >> 5, lane = threadIdx.x & 31;
    const int e = blockIdx.x * 8 + warp;
    float s = 0.f;
#pragma unroll
    for (int p = lane; p < 64; p += 32) s += g_L1part[p][e];
    const float* r2 = B2 + (size_t)e * Tt;
    for (int i = lane * 4; i < Tt; i += 128) {
        float4 v = *(const float4*)(r2 + i);
        s += v.x * v.x + v.y * v.y + v.z * v.z + v.w * v.w;
    }
#pragma unroll
    for (int o = 16; o; o >>= 1) s += __shfl_xor_sync(0xffffffffu, s, o);
    if (lane == 0) g_L1[e] = s;
}

// ---------------------------------------------------------------------------
// mma.sync GEMM core with ldmatrix fragments.
// C[128,128] += A[128,K]*B[128,K]^T, hi/lo bf16, 3-MMA fp32 emulation.
// K-tile 32, rows of 64B, XOR swizzle chunk' = chunk ^ ((row>>1)&3).
// 3-stage cp.async pipeline, 96KB smem -> 2 CTAs/SM. 8 warps = 2(m) x 4(n).
// R13: single __syncthreads per iter + B-fragment cross-kk prefetch.
// ---------------------------------------------------------------------------
#define KT        32
#define ROWBYTES  64
#define TILE_BS   8192                 // 128 rows * 64B
#define STAGE_BS  (4 * TILE_BS)        // Ahi Alo Bhi Blo = 32KB
#define NSTAGE    3
#define SMEM_DYN  (NSTAGE * STAGE_BS)  // 98304

__device__ __forceinline__ void load_tile32(uint32_t dst,
        const __nv_bfloat16* __restrict__ src, int ld, int k0, int tid) {
#pragma unroll
    for (int half = 0; half < 2; half++) {
        const int idx = half * 256 + tid;     // 0..511
        const int row = idx >> 2, c = idx & 3;
        const int sw = c ^ ((row >> 1) & 3);
        cp_async16(dst + (uint32_t)(row * ROWBYTES + sw * 16),
                   src + (size_t)row * ld + k0 + c * 8);
    }
}

__device__ __forceinline__ void load_stage(uint32_t sb,
    const __nv_bfloat16* Ahi, const __nv_bfloat16* Alo, int lda,
    const __nv_bfloat16* Bhi, const __nv_bfloat16* Blo, int ldb,
    int k0, int tid) {
    load_tile32(sb,               Ahi, lda, k0, tid);
    load_tile32(sb + TILE_BS,     Alo, lda, k0, tid);
    load_tile32(sb + 2 * TILE_BS, Bhi, ldb, k0, tid);
    load_tile32(sb + 3 * TILE_BS, Blo, ldb, k0, tid);
}

// Load one half (p) of the B fragments for chunk kk: 2 LDSM.x4 (hi+lo).
__device__ __forceinline__ void loadB_part(uint32_t sb_baddr, int p,
                                           uint32_t (&bh)[4][2], uint32_t (&bl)[4][2]) {
    uint32_t r0, r1, r2, r3;
    ldsm_x4(r0, r1, r2, r3, sb_baddr + p * 1024);
    bh[2 * p][0] = r0; bh[2 * p + 1][0] = r1;
    bh[2 * p][1] = r2; bh[2 * p + 1][1] = r3;
    ldsm_x4(r0, r1, r2, r3, sb_baddr + p * 1024 + TILE_BS);
    bl[2 * p][0] = r0; bl[2 * p + 1][0] = r1;
    bl[2 * p][1] = r2; bl[2 * p + 1][1] = r3;
}

__device__ __forceinline__ void gemm_mainloop(char* smem,
    const __nv_bfloat16* __restrict__ Ahi, const __nv_bfloat16* __restrict__ Alo, int lda,
    const __nv_bfloat16* __restrict__ Bhi, const __nv_bfloat16* __restrict__ Blo, int ldb,
    int nT, float (&acc)[4][4][4]) {
    const int tid = threadIdx.x;
    const int wid = tid >> 5, lane = tid & 31;
    const int wm = wid & 1, wn = wid >> 1;
    const int mat = lane >> 3, r = lane & 7;
    const int s = (r >> 1) & 3;
    const uint32_t su = smem_to_u32(smem);

    // Per-lane ldmatrix addresses (relative to stage base); swizzle constant
    // across mi/p/mat offsets (all multiples of 8 rows).
    uint32_t aAddr[2], bAddr[2];
#pragma unroll
    for (int kk = 0; kk < 2; kk++) {
        const int ch = (kk * 2 + (mat >> 1)) ^ s;
        aAddr[kk] = (uint32_t)((wm * 64 + (mat & 1) * 8 + r) * ROWBYTES + ch * 16);
        bAddr[kk] = (uint32_t)(2 * TILE_BS +
                               (wn * 32 + (mat & 1) * 8 + r) * ROWBYTES + ch * 16);
    }

    load_stage(su, Ahi, Alo, lda, Bhi, Blo, ldb, 0, tid);
    CP_COMMIT();
    load_stage(su + STAGE_BS, Ahi, Alo, lda, Bhi, Blo, ldb, KT, tid);
    CP_COMMIT();

    uint32_t sb_off = 0;  // (it % 3) * STAGE_BS
    for (int it = 0; it < nT; ++it) {
        if (it == nT - 1) { CP_WAIT(0); } else { CP_WAIT(1); }
        // Single barrier per iter: (a) stage `it` visible to all warps,
        // (b) all warps finished compute(it-1), whose stage (it-1)%3 ==
        //     (it+2)%3 is about to be overwritten by the loads below.
        __syncthreads();
        if (it + 2 < nT) {
            const uint32_t nb = (sb_off + 2 * STAGE_BS >= 3 * STAGE_BS)
                              ? sb_off - STAGE_BS : sb_off + 2 * STAGE_BS;
            load_stage(su + nb, Ahi, Alo, lda, Bhi, Blo, ldb, (it + 2) * KT, tid);
            CP_COMMIT();
        }

        const uint32_t sb = su + sb_off;
        uint32_t b0h[4][2], b0l[4][2], b1h[4][2], b1l[4][2];
        loadB_part(sb + bAddr[0], 0, b0h, b0l);
        loadB_part(sb + bAddr[0], 1, b0h, b0l);

        // kk = 0 (prefetch kk=1 B fragments inside the mi loop)
#pragma unroll
        for (int mi = 0; mi < 4; mi++) {
            uint32_t ah[4], al[4];
            ldsm_x4(ah[0], ah[1], ah[2], ah[3], sb + aAddr[0] + mi * 1024);
            ldsm_x4(al[0], al[1], al[2], al[3], sb + aAddr[0] + mi * 1024 + TILE_BS);
            if (mi < 2) loadB_part(sb + bAddr[1], mi, b1h, b1l);
#pragma unroll
            for (int ni = 0; ni < 4; ni++) mma_bf16(acc[mi][ni], ah, b0h[ni]);
#pragma unroll
            for (int ni = 0; ni < 4; ni++) mma_bf16(acc[mi][ni], ah, b0l[ni]);
#pragma unroll
            for (int ni = 0; ni < 4; ni++) mma_bf16(acc[mi][ni], al, b0h[ni]);
        }
        // kk = 1 (B fragments already in registers)
#pragma unroll
        for (int mi = 0; mi < 4; mi++) {
            uint32_t ah[4], al[4];
            ldsm_x4(ah[0], ah[1], ah[2], ah[3], sb + aAddr[1] + mi * 1024);
            ldsm_x4(al[0], al[1], al[2], al[3], sb + aAddr[1] + mi * 1024 + TILE_BS);
#pragma unroll
            for (int ni = 0; ni < 4; ni++) mma_bf16(acc[mi][ni], ah, b1h[ni]);
#pragma unroll
            for (int ni = 0; ni < 4; ni++) mma_bf16(acc[mi][ni], ah, b1l[ni]);
#pragma unroll
            for (int ni = 0; ni < 4; ni++) mma_bf16(acc[mi][ni], al, b1h[ni]);
        }
        sb_off = (sb_off + STAGE_BS >= 3 * STAGE_BS) ? 0 : sb_off + STAGE_BS;
    }
}

// GEMM1: EtT[cb*128+c][e] = L1[e] * sum_n B1T[e,n]*HT[cb][c][n]
// Epilogue: scale by L1, transpose in smem (fp32, stride 129), write EtT
// hi/lo directly with coalesced 256B rows. No Et32 round-trip.
__global__ __launch_bounds__(256, 2) void gemm1_kernel() {
    extern __shared__ char smem[];
    float acc[4][4][4];
#pragma unroll
    for (int i = 0; i < 4; i++)
#pragma unroll
        for (int j = 0; j < 4; j++)
#pragma unroll
            for (int k = 0; k < 4; k++) acc[i][j][k] = 0.f;

    const int m0 = blockIdx.x * 128;   // e block
    const int cb = blockIdx.y;         // batch
    gemm_mainloop(smem,
                  g_B1T_hi + (size_t)m0 * Nn, g_B1T_lo + (size_t)m0 * Nn, Nn,
                  g_HT_hi + (size_t)cb * HH * Nn, g_HT_lo + (size_t)cb * HH * Nn, Nn,
                  Nn / KT, acc);

    const int tid = threadIdx.x, lane = tid & 31, wid = tid >> 5;
    const int wm = wid & 1, wn = wid >> 1;
    const int g = lane >> 2, tig = lane & 3;

    __syncthreads();                       // mainloop smem reads done
    float* Cs = (float*)smem;              // [128 e][129] (pad -> conflict-lite)
#pragma unroll
    for (int mi = 0; mi < 4; mi++) {
        const int mr = wm * 64 + mi * 16 + g;       // e-local
        const float s0 = g_L1[m0 + mr], s1 = g_L1[m0 + mr + 8];
#pragma unroll
        for (int ni = 0; ni < 4; ni++) {
            const int nc = wn * 32 + ni * 8 + 2 * tig;   // c-local
            Cs[mr * 129 + nc]           = acc[mi][ni][0] * s0;
            Cs[mr * 129 + nc + 1]       = acc[mi][ni][1] * s0;
            Cs[(mr + 8) * 129 + nc]     = acc[mi][ni][2] * s1;
            Cs[(mr + 8) * 129 + nc + 1] = acc[mi][ni][3] * s1;
        }
    }
    __syncthreads();
    // Each warp writes 16 output rows (c); lane covers e-chunk [4l, 4l+4).
#pragma unroll
    for (int rr = 0; rr < 16; rr++) {
        const int c = wid * 16 + rr;
        __align__(8) __nv_bfloat16 hb[4], lb[4];
#pragma unroll
        for (int j = 0; j < 4; j++)
            bf16_split(Cs[(4 * lane + j) * 129 + c], hb[j], lb[j]);
        const size_t off = (size_t)(cb * 128 + c) * Ee + m0 + 4 * lane;
        *(uint2*)(g_EtT_hi + off) = *(const uint2*)hb;
        *(uint2*)(g_EtT_lo + off) = *(const uint2*)lb;
    }
}

// GEMM2 (K-split 2): dHp[sp][cb][n][h] = sum_{e in split sp} B1[n,e]*EtT[cb*128+h][e]
__global__ __launch_bounds__(256, 2) void gemm2_kernel() {
    extern __shared__ char smem[];
    float acc[4][4][4];
#pragma unroll
    for (int i = 0; i < 4; i++)
#pragma unroll
        for (int j = 0; j < 4; j++)
#pragma unroll
            for (int k = 0; k < 4; k++) acc[i][j][k] = 0.f;

    const int m0 = blockIdx.x * 128;   // n block
    const int cb = blockIdx.y;         // batch
    const int sp = blockIdx.z;         // K split
    const size_t ko = (size_t)sp * (Ee / 2);
    gemm_mainloop(smem,
                  g_B1_hi + (size_t)m0 * Ee + ko, g_B1_lo + (size_t)m0 * Ee + ko, Ee,
                  g_EtT_hi + (size_t)cb * 128 * Ee + ko,
                  g_EtT_lo + (size_t)cb * 128 * Ee + ko, Ee,
                  (Ee / 2) / KT, acc);

    const int tid = threadIdx.x, lane = tid & 31, wid = tid >> 5;
    const int wm = wid & 1, wn = wid >> 1;
    const int g = lane >> 2, tig = lane & 3;
    float* outb = g_dH + (size_t)sp * (Bb * Nn * HH);
#pragma unroll
    for (int mi = 0; mi < 4; mi++) {
        const int gn = m0 + wm * 64 + mi * 16 + g;
        float* r0 = outb + ((size_t)cb * Nn + gn) * HH;
        float* r1 = r0 + 8 * HH;
#pragma unroll
        for (int ni = 0; ni < 4; ni++) {
            const int h = wn * 32 + ni * 8 + 2 * tig;
            *(float2*)(r0 + h) = make_float2(acc[mi][ni][0], acc[mi][ni][1]);
            *(float2*)(r1 + h) = make_float2(acc[mi][ni][2], acc[mi][ni][3]);
        }
    }
}

// ---------------------------------------------------------------------------
// Final: out = H + alpha * relu( (dHp0+dHp1) @ W^T )
// ---------------------------------------------------------------------------
__global__ __launch_bounds__(256) void final_kernel(
    const float* __restrict__ H, const float* __restrict__ W,
    const float* __restrict__ alpha_raw, float* __restrict__ out) {
    __shared__ float As[32][132];
    __shared__ float Ws[32][132];
    const int tid = threadIdx.x;
    const int tx = tid & 15, ty = tid >> 4;
    const int m0 = blockIdx.x * 128;
    const int r = tid >> 3, c4 = (tid & 7) * 4;
    const size_t DHP = (size_t)Bb * Nn * HH;

    float acc[8][8];
#pragma unroll
    for (int i = 0; i < 8; i++)
#pragma unroll
        for (int j = 0; j < 8; j++) acc[i][j] = 0.f;

    for (int h0 = 0; h0 < HH; h0 += 32) {
        __syncthreads();
#pragma unroll
        for (int p = 0; p < 4; p++) {
            const int row = r + p * 32;
            const size_t ai = (size_t)(m0 + row) * HH + h0 + c4;
            float4 a0 = *(const float4*)(g_dH + ai);
            float4 a1 = *(const float4*)(g_dH + DHP + ai);
            As[c4 + 0][row] = a0.x + a1.x; As[c4 + 1][row] = a0.y + a1.y;
            As[c4 + 2][row] = a0.z + a1.z; As[c4 + 3][row] = a0.w + a1.w;
            float4 wv = *(const float4*)(W + (size_t)row * HH + h0 + c4);
            Ws[c4 + 0][row] = wv.x; Ws[c4 + 1][row] = wv.y;
            Ws[c4 + 2][row] = wv.z; Ws[c4 + 3][row] = wv.w;
        }
        __syncthreads();
#pragma unroll
        for (int kk = 0; kk < 32; kk++) {
            float a[8], w[8];
            *(float4*)(a)     = *(const float4*)&As[kk][ty * 8];
            *(float4*)(a + 4) = *(const float4*)&As[kk][ty * 8 + 4];
            *(float4*)(w)     = *(const float4*)&Ws[kk][tx * 8];
            *(float4*)(w + 4) = *(const float4*)&Ws[kk][tx * 8 + 4];
#pragma unroll
            for (int i = 0; i < 8; i++)
#pragma unroll
                for (int j = 0; j < 8; j++)
                    acc[i][j] = fmaf(a[i], w[j], acc[i][j]);
        }
    }

    const float alpha = 0.05f / (1.0f + expf(-alpha_raw[0]));
#pragma unroll
    for (int i = 0; i < 8; i++) {
        const size_t m = (size_t)m0 + ty * 8 + i;
        const float* Hr = H + m * HH + tx * 8;
        float* Or = out + m * HH + tx * 8;
#pragma unroll
        for (int j = 0; j < 8; j++)
            Or[j] = Hr[j] + alpha * fmaxf(acc[i][j], 0.f);
    }
}

// ---------------------------------------------------------------------------
extern "C" void kernel_launch(void* const* d_in, const int* in_sizes, int n_in,
                              void* d_out, int out_size) {
    const float* H  = (const float*)d_in[0];
    const float* B1 = (const float*)d_in[1];
    const float* B2 = (const float*)d_in[2];
    const float* W  = (const float*)d_in[3];
    const float* ar = (const float*)d_in[4];
    float* out = (float*)d_out;

    cudaFuncSetAttribute(gemm1_kernel, cudaFuncAttributeMaxDynamicSharedMemorySize, SMEM_DYN);
    cudaFuncSetAttribute(gemm2_kernel, cudaFuncAttributeMaxDynamicSharedMemorySize, SMEM_DYN);

    // B1 [N,E] -> B1T hi/lo [E,N] + B1 hi/lo [N,E] + L1 partials (one read)
    tsplit_b1_kernel<<<dim3(Ee / 32, Nn / 32, 1), dim3(32, 8)>>>(B1);
    // H [b][n][h] -> HT hi/lo [b][h][n]
    tsplit_h_kernel<<<dim3(HH / 32, Nn / 32, Bb), dim3(32, 8)>>>(H);
    // L1[e] = sum partials + rowsum(B2^2)
    l1_finalize_kernel<<<Ee / 8, 256>>>(B2);

    // GEMM1 -> EtT hi/lo [CD][E] directly (fused transpose epilogue)
    gemm1_kernel<<<dim3(Ee / 128, Bb), 256, SMEM_DYN>>>();
    // GEMM2 (K-split 2) -> dH partials
    gemm2_kernel<<<dim3(Nn / 128, Bb, 2), 256, SMEM_DYN>>>();
    final_kernel<<<(Bb * Nn) / 128, 256>>>(H, W, ar, out);
}

// round 14
// speedup vs baseline: 1.1120x; 1.1120x over previous
#include <cuda_runtime.h>
#include <cuda_bf16.h>
#include <cstdint>
#include <math.h>

// Problem dims
#define Bb   8
#define Nn   2048
#define Ee   8192
#define Tt   4096
#define HH   128
#define CD   1024   // B*HH

// ---------------------------------------------------------------------------
// Scratch (static device globals). NEVER pass these as kernel arguments from
// host code (host shadow symbol + GB300 ATS silently writes host memory —
// the R8/R9 bug). All bindings happen inside device code.
// ---------------------------------------------------------------------------
__device__ __nv_bfloat16 g_B1T_hi[(size_t)Ee * Nn];      // B1^T  [E,N]
__device__ __nv_bfloat16 g_B1T_lo[(size_t)Ee * Nn];
__device__ __nv_bfloat16 g_B1_hi [(size_t)Nn * Ee];      // B1    [N,E]
__device__ __nv_bfloat16 g_B1_lo [(size_t)Nn * Ee];
__device__ __nv_bfloat16 g_HT_hi [(size_t)Bb * HH * Nn]; // H^T [b][h][n]
__device__ __nv_bfloat16 g_HT_lo [(size_t)Bb * HH * Nn];
__device__ __nv_bfloat16 g_EtT_hi[(size_t)CD * Ee];      // Etopo^T [b*128+h][e]
__device__ __nv_bfloat16 g_EtT_lo[(size_t)CD * Ee];
__device__ float g_dH[(size_t)4 * Bb * Nn * HH];         // 4 K-split partials
__device__ float g_L1[Ee];
__device__ float g_L1part[64][Ee];

// ---------------------------------------------------------------------------
// Base-ISA helpers (sm_80 features only — plain compute_103 safe)
// ---------------------------------------------------------------------------
__device__ __forceinline__ uint32_t smem_to_u32(const void* p) {
    uint32_t a;
    asm("{ .reg .u64 t; cvta.to.shared.u64 t, %1; cvt.u32.u64 %0, t; }"
        : "=r"(a) : "l"(p));
    return a;
}
#define CP_COMMIT() asm volatile("cp.async.commit_group;" ::: "memory")
#define CP_WAIT(n)  asm volatile("cp.async.wait_group %0;" :: "n"(n) : "memory")

__device__ __forceinline__ void cp_async16(uint32_t dst, const void* src) {
    asm volatile("cp.async.cg.shared.global [%0], [%1], 16;" :: "r"(dst), "l"(src));
}
__device__ __forceinline__ void ldsm_x4(uint32_t& r0, uint32_t& r1,
                                        uint32_t& r2, uint32_t& r3, uint32_t a) {
    asm volatile("ldmatrix.sync.aligned.m8n8.x4.shared.b16 {%0,%1,%2,%3}, [%4];"
                 : "=r"(r0), "=r"(r1), "=r"(r2), "=r"(r3) : "r"(a));
}
__device__ __forceinline__ void mma_bf16(float d[4], const uint32_t a[4],
                                         const uint32_t b[2]) {
    asm volatile(
        "mma.sync.aligned.m16n8k16.row.col.f32.bf16.bf16.f32 "
        "{%0,%1,%2,%3}, {%4,%5,%6,%7}, {%8,%9}, {%0,%1,%2,%3};"
        : "+f"(d[0]), "+f"(d[1]), "+f"(d[2]), "+f"(d[3])
        : "r"(a[0]), "r"(a[1]), "r"(a[2]), "r"(a[3]), "r"(b[0]), "r"(b[1]));
}
__device__ __forceinline__ void bf16_split(float a, __nv_bfloat16& h, __nv_bfloat16& l) {
    h = __float2bfloat16(a);
    l = __float2bfloat16(a - __bfloat162float(h));
}

// ---------------------------------------------------------------------------
// Prep kernels. tsplit = 32x32 transpose + bf16 hi/lo split.
// ---------------------------------------------------------------------------
__device__ __forceinline__ void tsplit_body(
    const float* __restrict__ in, int ld_in,
    __nv_bfloat16* __restrict__ hi, __nv_bfloat16* __restrict__ lo,
    int ld_out) {
    __shared__ float t[32][33];
    const int r0 = blockIdx.y * 32, c0 = blockIdx.x * 32;
    const int x = threadIdx.x, y = threadIdx.y;
#pragma unroll
    for (int i = 0; i < 32; i += 8)
        t[y + i][x] = in[(size_t)(r0 + y + i) * ld_in + c0 + x];
    __syncthreads();
#pragma unroll
    for (int i = 0; i < 32; i += 8) {
        float v = t[x][y + i];
        __nv_bfloat16 h, l;
        bf16_split(v, h, l);
        size_t o = (size_t)(c0 + y + i) * ld_out + r0 + x;
        hi[o] = h; lo[o] = l;
    }
}

// B1 [N,E]: emits B1T hi/lo [E,N] (transposed), B1 hi/lo [N,E] (straight),
// and per-32-row-block L1 partial sums. One read of B1.
__global__ void tsplit_b1_kernel(const float* __restrict__ B1) {
    __shared__ float t[32][33];
    __shared__ float ps[8][32];
    const int r0 = blockIdx.y * 32, c0 = blockIdx.x * 32;
    const int x = threadIdx.x, y = threadIdx.y;
    float s = 0.f;
#pragma unroll
    for (int i = 0; i < 32; i += 8) {
        float v = B1[(size_t)(r0 + y + i) * Ee + c0 + x];
        t[y + i][x] = v;
        s += v * v;
        __nv_bfloat16 h, l;
        bf16_split(v, h, l);
        const size_t o = (size_t)(r0 + y + i) * Ee + c0 + x;
        g_B1_hi[o] = h; g_B1_lo[o] = l;
    }
    ps[y][x] = s;
    __syncthreads();
    if (y == 0) {
        float tot = 0.f;
#pragma unroll
        for (int k = 0; k < 8; k++) tot += ps[k][x];
        g_L1part[blockIdx.y][c0 + x] = tot;
    }
#pragma unroll
    for (int i = 0; i < 32; i += 8) {
        float v = t[x][y + i];
        __nv_bfloat16 h, l;
        bf16_split(v, h, l);
        size_t o = (size_t)(c0 + y + i) * Nn + r0 + x;
        g_B1T_hi[o] = h; g_B1T_lo[o] = l;
    }
}

// H [b][n][h] -> g_HT hi/lo [b][h][n]
__global__ void tsplit_h_kernel(const float* __restrict__ H) {
    const size_t ib = (size_t)blockIdx.z * (Nn * HH);
    const size_t ob = (size_t)blockIdx.z * (HH * Nn);
    tsplit_body(H + ib, HH, g_HT_hi + ob, g_HT_lo + ob, Nn);
}

__global__ void l1_finalize_kernel(const float* __restrict__ B2) {
    const int warp = threadIdx.x >> 5, lane = threadIdx.x & 31;
    const int e = blockIdx.x * 8 + warp;
    float s = 0.f;
#pragma unroll
    for (int p = lane; p < 64; p += 32) s += g_L1part[p][e];
    const float* r2 = B2 + (size_t)e * Tt;
    for (int i = lane * 4; i < Tt; i += 128) {
        float4 v = *(const float4*)(r2 + i);
        s += v.x * v.x + v.y * v.y + v.z * v.z + v.w * v.w;
    }
#pragma unroll
    for (int o = 16; o; o >>= 1) s += __shfl_xor_sync(0xffffffffu, s, o);
    if (lane == 0) g_L1[e] = s;
}

// ---------------------------------------------------------------------------
// mma.sync GEMM core with ldmatrix fragments.
// C[64,128] += A[64,K]*B[128,K]^T, hi/lo bf16, 3-MMA fp32 emulation.
// R14: 64x128 CTA tile, warp tile 32x32 (acc 32 regs) -> 3 CTAs/SM,
// 24 warps/SM = 6/SMSP. K-tile 32, 64B rows, XOR swizzle
// chunk' = chunk ^ ((row>>1)&3). 3-stage cp.async pipeline (24KB/stage).
// 8 warps = 2(m) x 4(n).
// ---------------------------------------------------------------------------
#define KT        32
#define ROWBYTES  64
#define TILE_A    4096                 // 64 rows * 64B
#define TILE_B    8192                 // 128 rows * 64B
#define STAGE_BS  (2 * TILE_A + 2 * TILE_B)   // 24576
#define SMEM_DYN  (3 * STAGE_BS)              // 73728

__device__ __forceinline__ void load_tile32(uint32_t dst,
        const __nv_bfloat16* __restrict__ src, int ld, int k0,
        int tid, int nrows) {
    for (int idx = tid; idx < nrows * 4; idx += 256) {
        const int row = idx >> 2, c = idx & 3;
        const int sw = c ^ ((row >> 1) & 3);
        cp_async16(dst + (uint32_t)(row * ROWBYTES + sw * 16),
                   src + (size_t)row * ld + k0 + c * 8);
    }
}

__device__ __forceinline__ void load_stage(uint32_t sb,
    const __nv_bfloat16* Ahi, const __nv_bfloat16* Alo, int lda,
    const __nv_bfloat16* Bhi, const __nv_bfloat16* Blo, int ldb,
    int k0, int tid) {
    load_tile32(sb,                       Ahi, lda, k0, tid, 64);
    load_tile32(sb + TILE_A,              Alo, lda, k0, tid, 64);
    load_tile32(sb + 2 * TILE_A,          Bhi, ldb, k0, tid, 128);
    load_tile32(sb + 2 * TILE_A + TILE_B, Blo, ldb, k0, tid, 128);
}

__device__ __forceinline__ void gemm_mainloop(char* smem,
    const __nv_bfloat16* __restrict__ Ahi, const __nv_bfloat16* __restrict__ Alo, int lda,
    const __nv_bfloat16* __restrict__ Bhi, const __nv_bfloat16* __restrict__ Blo, int ldb,
    int nT, float (&acc)[2][4][4]) {
    const int tid = threadIdx.x;
    const int wid = tid >> 5, lane = tid & 31;
    const int wm = wid & 1, wn = wid >> 1;
    const int mat = lane >> 3, r = lane & 7;
    const int s = (r >> 1) & 3;
    const uint32_t su = smem_to_u32(smem);

    // Per-lane ldmatrix addresses; swizzle constant across mi/p/mat offsets
    // (all multiples of 8 rows).
    uint32_t aAddr[2], bAddr[2];
#pragma unroll
    for (int kk = 0; kk < 2; kk++) {
        const int ch = (kk * 2 + (mat >> 1)) ^ s;
        aAddr[kk] = (uint32_t)((wm * 32 + (mat & 1) * 8 + r) * ROWBYTES + ch * 16);
        bAddr[kk] = (uint32_t)(2 * TILE_A +
                               (wn * 32 + (mat & 1) * 8 + r) * ROWBYTES + ch * 16);
    }

    load_stage(su, Ahi, Alo, lda, Bhi, Blo, ldb, 0, tid);
    CP_COMMIT();
    load_stage(su + STAGE_BS, Ahi, Alo, lda, Bhi, Blo, ldb, KT, tid);
    CP_COMMIT();

    uint32_t sb_off = 0;  // (it % 3) * STAGE_BS
    for (int it = 0; it < nT; ++it) {
        if (it == nT - 1) { CP_WAIT(0); } else { CP_WAIT(1); }
        __syncthreads();
        if (it + 2 < nT) {
            const uint32_t nb = (sb_off + 2 * STAGE_BS >= 3 * STAGE_BS)
                              ? sb_off - STAGE_BS : sb_off + 2 * STAGE_BS;
            load_stage(su + nb, Ahi, Alo, lda, Bhi, Blo, ldb, (it + 2) * KT, tid);
            CP_COMMIT();
        }

        const uint32_t sb = su + sb_off;
#pragma unroll
        for (int kk = 0; kk < 2; kk++) {
            uint32_t bh[4][2], bl[4][2];
#pragma unroll
            for (int p = 0; p < 2; p++) {
                uint32_t r0, r1, r2, r3;
                ldsm_x4(r0, r1, r2, r3, sb + bAddr[kk] + p * 1024);
                bh[2 * p][0] = r0; bh[2 * p + 1][0] = r1;
                bh[2 * p][1] = r2; bh[2 * p + 1][1] = r3;
                ldsm_x4(r0, r1, r2, r3, sb + bAddr[kk] + p * 1024 + TILE_B);
                bl[2 * p][0] = r0; bl[2 * p + 1][0] = r1;
                bl[2 * p][1] = r2; bl[2 * p + 1][1] = r3;
            }
#pragma unroll
            for (int mi = 0; mi < 2; mi++) {
                uint32_t ah[4], al[4];
                ldsm_x4(ah[0], ah[1], ah[2], ah[3], sb + aAddr[kk] + mi * 1024);
                ldsm_x4(al[0], al[1], al[2], al[3],
                        sb + aAddr[kk] + mi * 1024 + TILE_A);
#pragma unroll
                for (int ni = 0; ni < 4; ni++) mma_bf16(acc[mi][ni], ah, bh[ni]);
#pragma unroll
                for (int ni = 0; ni < 4; ni++) mma_bf16(acc[mi][ni], ah, bl[ni]);
#pragma unroll
                for (int ni = 0; ni < 4; ni++) mma_bf16(acc[mi][ni], al, bh[ni]);
            }
        }
        sb_off = (sb_off + STAGE_BS >= 3 * STAGE_BS) ? 0 : sb_off + STAGE_BS;
    }
}

// GEMM1: EtT[cb*128+c][e] = L1[e] * sum_n B1T[e,n]*HT[cb][c][n]
// Epilogue: L1-scale, transpose via smem (fp32 [64][129]), bf16-split,
// coalesced 128B-row writes. No fp32 round-trip through global.
__global__ __launch_bounds__(256, 3) void gemm1_kernel() {
    extern __shared__ char smem[];
    float acc[2][4][4];
#pragma unroll
    for (int i = 0; i < 2; i++)
#pragma unroll
        for (int j = 0; j < 4; j++)
#pragma unroll
            for (int k = 0; k < 4; k++) acc[i][j][k] = 0.f;

    const int m0 = blockIdx.x * 64;    // e block
    const int cb = blockIdx.y;         // batch
    gemm_mainloop(smem,
                  g_B1T_hi + (size_t)m0 * Nn, g_B1T_lo + (size_t)m0 * Nn, Nn,
                  g_HT_hi + (size_t)cb * HH * Nn, g_HT_lo + (size_t)cb * HH * Nn, Nn,
                  Nn / KT, acc);

    const int tid = threadIdx.x, lane = tid & 31, wid = tid >> 5;
    const int wm = wid & 1, wn = wid >> 1;
    const int g = lane >> 2, tig = lane & 3;

    __syncthreads();                       // mainloop smem reads done
    float* Cs = (float*)smem;              // [64 e][129]
#pragma unroll
    for (int mi = 0; mi < 2; mi++) {
        const int mr = wm * 32 + mi * 16 + g;       // e-local
        const float s0 = g_L1[m0 + mr], s1 = g_L1[m0 + mr + 8];
#pragma unroll
        for (int ni = 0; ni < 4; ni++) {
            const int nc = wn * 32 + ni * 8 + 2 * tig;   // c-local
            Cs[mr * 129 + nc]           = acc[mi][ni][0] * s0;
            Cs[mr * 129 + nc + 1]       = acc[mi][ni][1] * s0;
            Cs[(mr + 8) * 129 + nc]     = acc[mi][ni][2] * s1;
            Cs[(mr + 8) * 129 + nc + 1] = acc[mi][ni][3] * s1;
        }
    }
    __syncthreads();
    // Each warp writes 16 output c-rows; lane covers e-chunk [2l, 2l+2).
#pragma unroll
    for (int rr = 0; rr < 16; rr++) {
        const int c = wid * 16 + rr;
        __nv_bfloat16 hb[2], lb[2];
        bf16_split(Cs[(2 * lane) * 129 + c],     hb[0], lb[0]);
        bf16_split(Cs[(2 * lane + 1) * 129 + c], hb[1], lb[1]);
        const size_t off = (size_t)(cb * 128 + c) * Ee + m0 + 2 * lane;
        *(uint32_t*)(g_EtT_hi + off) = *(const uint32_t*)hb;
        *(uint32_t*)(g_EtT_lo + off) = *(const uint32_t*)lb;
    }
}

// GEMM2 (K-split 4): dHp[sp][cb][n][h] = sum_{e in split sp} B1[n,e]*EtT[cb*128+h][e]
__global__ __launch_bounds__(256, 3) void gemm2_kernel() {
    extern __shared__ char smem[];
    float acc[2][4][4];
#pragma unroll
    for (int i = 0; i < 2; i++)
#pragma unroll
        for (int j = 0; j < 4; j++)
#pragma unroll
            for (int k = 0; k < 4; k++) acc[i][j][k] = 0.f;

    const int m0 = blockIdx.x * 64;    // n block
    const int cb = blockIdx.y;         // batch
    const int sp = blockIdx.z;         // K split
    const size_t ko = (size_t)sp * (Ee / 4);
    gemm_mainloop(smem,
                  g_B1_hi + (size_t)m0 * Ee + ko, g_B1_lo + (size_t)m0 * Ee + ko, Ee,
                  g_EtT_hi + (size_t)cb * 128 * Ee + ko,
                  g_EtT_lo + (size_t)cb * 128 * Ee + ko, Ee,
                  (Ee / 4) / KT, acc);

    const int tid = threadIdx.x, lane = tid & 31, wid = tid >> 5;
    const int wm = wid & 1, wn = wid >> 1;
    const int g = lane >> 2, tig = lane & 3;
    float* outb = g_dH + (size_t)sp * (Bb * Nn * HH);
#pragma unroll
    for (int mi = 0; mi < 2; mi++) {
        const int gn = m0 + wm * 32 + mi * 16 + g;
        float* r0 = outb + ((size_t)cb * Nn + gn) * HH;
        float* r1 = r0 + 8 * HH;
#pragma unroll
        for (int ni = 0; ni < 4; ni++) {
            const int h = wn * 32 + ni * 8 + 2 * tig;
            *(float2*)(r0 + h) = make_float2(acc[mi][ni][0], acc[mi][ni][1]);
            *(float2*)(r1 + h) = make_float2(acc[mi][ni][2], acc[mi][ni][3]);
        }
    }
}

// ---------------------------------------------------------------------------
// Final: out = H + alpha * relu( (dHp0+dHp1+dHp2+dHp3) @ W^T )
// ---------------------------------------------------------------------------
__global__ __launch_bounds__(256) void final_kernel(
    const float* __restrict__ H, const float* __restrict__ W,
    const float* __restrict__ alpha_raw, float* __restrict__ out) {
    __shared__ float As[32][132];
    __shared__ float Ws[32][132];
    const int tid = threadIdx.x;
    const int tx = tid & 15, ty = tid >> 4;
    const int m0 = blockIdx.x * 128;
    const int r = tid >> 3, c4 = (tid & 7) * 4;
    const size_t DHP = (size_t)Bb * Nn * HH;

    float acc[8][8];
#pragma unroll
    for (int i = 0; i < 8; i++)
#pragma unroll
        for (int j = 0; j < 8; j++) acc[i][j] = 0.f;

    for (int h0 = 0; h0 < HH; h0 += 32) {
        __syncthreads();
#pragma unroll
        for (int p = 0; p < 4; p++) {
            const int row = r + p * 32;
            const size_t ai = (size_t)(m0 + row) * HH + h0 + c4;
            float4 a0 = *(const float4*)(g_dH + ai);
            float4 a1 = *(const float4*)(g_dH + DHP + ai);
            float4 a2 = *(const float4*)(g_dH + 2 * DHP + ai);
            float4 a3 = *(const float4*)(g_dH + 3 * DHP + ai);
            As[c4 + 0][row] = (a0.x + a1.x) + (a2.x + a3.x);
            As[c4 + 1][row] = (a0.y + a1.y) + (a2.y + a3.y);
            As[c4 + 2][row] = (a0.z + a1.z) + (a2.z + a3.z);
            As[c4 + 3][row] = (a0.w + a1.w) + (a2.w + a3.w);
            float4 wv = *(const float4*)(W + (size_t)row * HH + h0 + c4);
            Ws[c4 + 0][row] = wv.x; Ws[c4 + 1][row] = wv.y;
            Ws[c4 + 2][row] = wv.z; Ws[c4 + 3][row] = wv.w;
        }
        __syncthreads();
#pragma unroll
        for (int kk = 0; kk < 32; kk++) {
            float a[8], w[8];
            *(float4*)(a)     = *(const float4*)&As[kk][ty * 8];
            *(float4*)(a + 4) = *(const float4*)&As[kk][ty * 8 + 4];
            *(float4*)(w)     = *(const float4*)&Ws[kk][tx * 8];
            *(float4*)(w + 4) = *(const float4*)&Ws[kk][tx * 8 + 4];
#pragma unroll
            for (int i = 0; i < 8; i++)
#pragma unroll
                for (int j = 0; j < 8; j++)
                    acc[i][j] = fmaf(a[i], w[j], acc[i][j]);
        }
    }

    const float alpha = 0.05f / (1.0f + expf(-alpha_raw[0]));
#pragma unroll
    for (int i = 0; i < 8; i++) {
        const size_t m = (size_t)m0 + ty * 8 + i;
        const float* Hr = H + m * HH + tx * 8;
        float* Or = out + m * HH + tx * 8;
#pragma unroll
        for (int j = 0; j < 8; j++)
            Or[j] = Hr[j] + alpha * fmaxf(acc[i][j], 0.f);
    }
}

// ---------------------------------------------------------------------------
extern "C" void kernel_launch(void* const* d_in, const int* in_sizes, int n_in,
                              void* d_out, int out_size) {
    const float* H  = (const float*)d_in[0];
    const float* B1 = (const float*)d_in[1];
    const float* B2 = (const float*)d_in[2];
    const float* W  = (const float*)d_in[3];
    const float* ar = (const float*)d_in[4];
    float* out = (float*)d_out;

    cudaFuncSetAttribute(gemm1_kernel, cudaFuncAttributeMaxDynamicSharedMemorySize, SMEM_DYN);
    cudaFuncSetAttribute(gemm2_kernel, cudaFuncAttributeMaxDynamicSharedMemorySize, SMEM_DYN);

    // B1 [N,E] -> B1T hi/lo [E,N] + B1 hi/lo [N,E] + L1 partials (one read)
    tsplit_b1_kernel<<<dim3(Ee / 32, Nn / 32, 1), dim3(32, 8)>>>(B1);
    // H [b][n][h] -> HT hi/lo [b][h][n]
    tsplit_h_kernel<<<dim3(HH / 32, Nn / 32, Bb), dim3(32, 8)>>>(H);
    // L1[e] = sum partials + rowsum(B2^2)
    l1_finalize_kernel<<<Ee / 8, 256>>>(B2);

    // GEMM1 -> EtT hi/lo [CD][E] directly (fused transpose epilogue)
    gemm1_kernel<<<dim3(Ee / 64, Bb), 256, SMEM_DYN>>>();
    // GEMM2 (K-split 4) -> dH partials
    gemm2_kernel<<<dim3(Nn / 64, Bb, 4), 256, SMEM_DYN>>>();
    final_kernel<<<(Bb * Nn) / 128, 256>>>(H, W, ar, out);
}

// round 15
// speedup vs baseline: 1.1665x; 1.0490x over previous
#include <cuda_runtime.h>
#include <cuda_bf16.h>
#include <cstdint>
#include <math.h>

// Problem dims
#define Bb   8
#define Nn   2048
#define Ee   8192
#define Tt   4096
#define HH   128
#define CD   1024   // B*HH

// ---------------------------------------------------------------------------
// Scratch (static device globals). NEVER pass these as kernel arguments from
// host code (host shadow symbol + GB300 ATS silently writes host memory —
// the R8/R9 bug). All bindings happen inside device code.
// ---------------------------------------------------------------------------
__device__ __nv_bfloat16 g_B1T_hi[(size_t)Ee * Nn];      // B1^T  [E,N]
__device__ __nv_bfloat16 g_B1T_lo[(size_t)Ee * Nn];
__device__ __nv_bfloat16 g_B1_hi [(size_t)Nn * Ee];      // B1    [N,E]
__device__ __nv_bfloat16 g_B1_lo [(size_t)Nn * Ee];
__device__ __nv_bfloat16 g_HT_hi [(size_t)Bb * HH * Nn]; // H^T [b][h][n]
__device__ __nv_bfloat16 g_HT_lo [(size_t)Bb * HH * Nn];
__device__ __nv_bfloat16 g_EtT_hi[(size_t)CD * Ee];      // Etopo^T [b*128+h][e]
__device__ __nv_bfloat16 g_EtT_lo[(size_t)CD * Ee];
__device__ float g_dH[(size_t)4 * Bb * Nn * HH];         // 4 K-split partials
__device__ float g_L1[Ee];
__device__ float g_L1part[64][Ee];

// ---------------------------------------------------------------------------
// Base-ISA helpers (sm_80 features only — plain compute_103 safe)
// ---------------------------------------------------------------------------
__device__ __forceinline__ uint32_t smem_to_u32(const void* p) {
    uint32_t a;
    asm("{ .reg .u64 t; cvta.to.shared.u64 t, %1; cvt.u32.u64 %0, t; }"
        : "=r"(a) : "l"(p));
    return a;
}
#define CP_COMMIT() asm volatile("cp.async.commit_group;" ::: "memory")
#define CP_WAIT(n)  asm volatile("cp.async.wait_group %0;" :: "n"(n) : "memory")

__device__ __forceinline__ void cp_async16(uint32_t dst, const void* src) {
    asm volatile("cp.async.cg.shared.global [%0], [%1], 16;" :: "r"(dst), "l"(src));
}
__device__ __forceinline__ void ldsm_x4(uint32_t& r0, uint32_t& r1,
                                        uint32_t& r2, uint32_t& r3, uint32_t a) {
    asm volatile("ldmatrix.sync.aligned.m8n8.x4.shared.b16 {%0,%1,%2,%3}, [%4];"
                 : "=r"(r0), "=r"(r1), "=r"(r2), "=r"(r3) : "r"(a));
}
__device__ __forceinline__ void mma_bf16(float d[4], const uint32_t a[4],
                                         const uint32_t b[2]) {
    asm volatile(
        "mma.sync.aligned.m16n8k16.row.col.f32.bf16.bf16.f32 "
        "{%0,%1,%2,%3}, {%4,%5,%6,%7}, {%8,%9}, {%0,%1,%2,%3};"
        : "+f"(d[0]), "+f"(d[1]), "+f"(d[2]), "+f"(d[3])
        : "r"(a[0]), "r"(a[1]), "r"(a[2]), "r"(a[3]), "r"(b[0]), "r"(b[1]));
}
__device__ __forceinline__ void bf16_split(float a, __nv_bfloat16& h, __nv_bfloat16& l) {
    h = __float2bfloat16(a);
    l = __float2bfloat16(a - __bfloat162float(h));
}

// ---------------------------------------------------------------------------
// Prep kernels. tsplit = 32x32 transpose + bf16 hi/lo split.
// ---------------------------------------------------------------------------
__device__ __forceinline__ void tsplit_body(
    const float* __restrict__ in, int ld_in,
    __nv_bfloat16* __restrict__ hi, __nv_bfloat16* __restrict__ lo,
    int ld_out) {
    __shared__ float t[32][33];
    const int r0 = blockIdx.y * 32, c0 = blockIdx.x * 32;
    const int x = threadIdx.x, y = threadIdx.y;
#pragma unroll
    for (int i = 0; i < 32; i += 8)
        t[y + i][x] = in[(size_t)(r0 + y + i) * ld_in + c0 + x];
    __syncthreads();
#pragma unroll
    for (int i = 0; i < 32; i += 8) {
        float v = t[x][y + i];
        __nv_bfloat16 h, l;
        bf16_split(v, h, l);
        size_t o = (size_t)(c0 + y + i) * ld_out + r0 + x;
        hi[o] = h; lo[o] = l;
    }
}

// B1 [N,E]: emits B1T hi/lo [E,N] (transposed), B1 hi/lo [N,E] (straight),
// and per-32-row-block L1 partial sums. One read of B1.
__global__ void tsplit_b1_kernel(const float* __restrict__ B1) {
    __shared__ float t[32][33];
    __shared__ float ps[8][32];
    const int r0 = blockIdx.y * 32, c0 = blockIdx.x * 32;
    const int x = threadIdx.x, y = threadIdx.y;
    float s = 0.f;
#pragma unroll
    for (int i = 0; i < 32; i += 8) {
        float v = B1[(size_t)(r0 + y + i) * Ee + c0 + x];
        t[y + i][x] = v;
        s += v * v;
        __nv_bfloat16 h, l;
        bf16_split(v, h, l);
        const size_t o = (size_t)(r0 + y + i) * Ee + c0 + x;
        g_B1_hi[o] = h; g_B1_lo[o] = l;
    }
    ps[y][x] = s;
    __syncthreads();
    if (y == 0) {
        float tot = 0.f;
#pragma unroll
        for (int k = 0; k < 8; k++) tot += ps[k][x];
        g_L1part[blockIdx.y][c0 + x] = tot;
    }
#pragma unroll
    for (int i = 0; i < 32; i += 8) {
        float v = t[x][y + i];
        __nv_bfloat16 h, l;
        bf16_split(v, h, l);
        size_t o = (size_t)(c0 + y + i) * Nn + r0 + x;
        g_B1T_hi[o] = h; g_B1T_lo[o] = l;
    }
}

// H [b][n][h] -> g_HT hi/lo [b][h][n]
__global__ void tsplit_h_kernel(const float* __restrict__ H) {
    const size_t ib = (size_t)blockIdx.z * (Nn * HH);
    const size_t ob = (size_t)blockIdx.z * (HH * Nn);
    tsplit_body(H + ib, HH, g_HT_hi + ob, g_HT_lo + ob, Nn);
}

__global__ void l1_finalize_kernel(const float* __restrict__ B2) {
    const int warp = threadIdx.x >> 5, lane = threadIdx.x & 31;
    const int e = blockIdx.x * 8 + warp;
    float s = 0.f;
#pragma unroll
    for (int p = lane; p < 64; p += 32) s += g_L1part[p][e];
    const float* r2 = B2 + (size_t)e * Tt;
    for (int i = lane * 4; i < Tt; i += 128) {
        float4 v = *(const float4*)(r2 + i);
        s += v.x * v.x + v.y * v.y + v.z * v.z + v.w * v.w;
    }
#pragma unroll
    for (int o = 16; o; o >>= 1) s += __shfl_xor_sync(0xffffffffu, s, o);
    if (lane == 0) g_L1[e] = s;
}

// ---------------------------------------------------------------------------
// mma.sync GEMM core with ldmatrix fragments.
// C[64,64] += A[64,K]*B[64,K]^T, hi/lo bf16, 3-MMA fp32 emulation.
// R15: 64x64 CTA tile, 128 threads (4 warps, 2m x 2n), warp tile 32x32
// unchanged -> 6 CTAs/SM (24 warps/SM), independent-CTA phase decorrelation.
// K-tile 32, 64B rows, XOR swizzle chunk' = chunk ^ ((row>>1)&3).
// 2-stage cp.async pipeline (16KB/stage, 32KB total).
// ---------------------------------------------------------------------------
#define KT        32
#define ROWBYTES  64
#define TILE_A    4096                 // 64 rows * 64B
#define TILE_B    4096                 // 64 rows * 64B
#define STAGE_BS  (2 * TILE_A + 2 * TILE_B)   // 16384
#define SMEM_DYN  (2 * STAGE_BS)              // 32768

// Shared addressing: one row/swizzle computation feeds 4 cp.async (A/B x hi/lo).
__device__ __forceinline__ void load_stage(uint32_t sb,
    const __nv_bfloat16* Ahi, const __nv_bfloat16* Alo, int lda,
    const __nv_bfloat16* Bhi, const __nv_bfloat16* Blo, int ldb,
    int k0, int tid) {
#pragma unroll
    for (int h = 0; h < 2; h++) {
        const int idx = tid + h * 128;        // 0..255 (64 rows x 4 chunks)
        const int row = idx >> 2, c = idx & 3;
        const uint32_t d = (uint32_t)(row * ROWBYTES + ((c ^ ((row >> 1) & 3)) * 16));
        const int co = k0 + c * 8;
        const size_t soa = (size_t)row * lda + co;
        const size_t sob = (size_t)row * ldb + co;
        cp_async16(sb + d,                      Ahi + soa);
        cp_async16(sb + TILE_A + d,             Alo + soa);
        cp_async16(sb + 2 * TILE_A + d,         Bhi + sob);
        cp_async16(sb + 2 * TILE_A + TILE_B + d, Blo + sob);
    }
}

__device__ __forceinline__ void gemm_mainloop(char* smem,
    const __nv_bfloat16* __restrict__ Ahi, const __nv_bfloat16* __restrict__ Alo, int lda,
    const __nv_bfloat16* __restrict__ Bhi, const __nv_bfloat16* __restrict__ Blo, int ldb,
    int nT, float (&acc)[2][4][4]) {
    const int tid = threadIdx.x;
    const int wid = tid >> 5, lane = tid & 31;
    const int wm = wid & 1, wn = wid >> 1;    // 2m x 2n warp grid
    const int mat = lane >> 3, r = lane & 7;
    const int s = (r >> 1) & 3;
    const uint32_t su = smem_to_u32(smem);

    // Per-lane ldmatrix addresses; swizzle constant across mi/p/mat offsets
    // (all multiples of 8 rows).
    uint32_t aAddr[2], bAddr[2];
#pragma unroll
    for (int kk = 0; kk < 2; kk++) {
        const int ch = (kk * 2 + (mat >> 1)) ^ s;
        aAddr[kk] = (uint32_t)((wm * 32 + (mat & 1) * 8 + r) * ROWBYTES + ch * 16);
        bAddr[kk] = (uint32_t)(2 * TILE_A +
                               (wn * 32 + (mat & 1) * 8 + r) * ROWBYTES + ch * 16);
    }

    load_stage(su, Ahi, Alo, lda, Bhi, Blo, ldb, 0, tid);
    CP_COMMIT();
    load_stage(su + STAGE_BS, Ahi, Alo, lda, Bhi, Blo, ldb, KT, tid);
    CP_COMMIT();

    for (int it = 0; it < nT; ++it) {
        if (it == nT - 1) { CP_WAIT(0); } else { CP_WAIT(1); }
        __syncthreads();

        const uint32_t sb = su + (uint32_t)(it & 1) * STAGE_BS;
#pragma unroll
        for (int kk = 0; kk < 2; kk++) {
            uint32_t bh[4][2], bl[4][2];
#pragma unroll
            for (int p = 0; p < 2; p++) {
                uint32_t r0, r1, r2, r3;
                ldsm_x4(r0, r1, r2, r3, sb + bAddr[kk] + p * 1024);
                bh[2 * p][0] = r0; bh[2 * p + 1][0] = r1;
                bh[2 * p][1] = r2; bh[2 * p + 1][1] = r3;
                ldsm_x4(r0, r1, r2, r3, sb + bAddr[kk] + p * 1024 + TILE_B);
                bl[2 * p][0] = r0; bl[2 * p + 1][0] = r1;
                bl[2 * p][1] = r2; bl[2 * p + 1][1] = r3;
            }
#pragma unroll
            for (int mi = 0; mi < 2; mi++) {
                uint32_t ah[4], al[4];
                ldsm_x4(ah[0], ah[1], ah[2], ah[3], sb + aAddr[kk] + mi * 1024);
                ldsm_x4(al[0], al[1], al[2], al[3],
                        sb + aAddr[kk] + mi * 1024 + TILE_A);
#pragma unroll
                for (int ni = 0; ni < 4; ni++) mma_bf16(acc[mi][ni], ah, bh[ni]);
#pragma unroll
                for (int ni = 0; ni < 4; ni++) mma_bf16(acc[mi][ni], ah, bl[ni]);
#pragma unroll
                for (int ni = 0; ni < 4; ni++) mma_bf16(acc[mi][ni], al, bh[ni]);
            }
        }

        if (it + 2 < nT) {
            __syncthreads();   // all warps done reading buf (it&1) before refill
            load_stage(sb, Ahi, Alo, lda, Bhi, Blo, ldb, (it + 2) * KT, tid);
            CP_COMMIT();
        }
    }
}

// GEMM1: EtT[b*128+h][e] = L1[e] * sum_n B1T[e,n]*HT[b][h][n]
// Grid: x = e-tile (E/64), y = (b<<1)|hb with hb the 64-col half of h.
// Epilogue: L1-scale, transpose via smem (fp32 [64][65]), bf16-split,
// coalesced 128B-row writes.
__global__ __launch_bounds__(128, 6) void gemm1_kernel() {
    extern __shared__ char smem[];
    float acc[2][4][4];
#pragma unroll
    for (int i = 0; i < 2; i++)
#pragma unroll
        for (int j = 0; j < 4; j++)
#pragma unroll
            for (int k = 0; k < 4; k++) acc[i][j][k] = 0.f;

    const int m0 = blockIdx.x * 64;        // e block
    const int b  = blockIdx.y >> 1;        // batch
    const int hb = blockIdx.y & 1;         // h half (64 cols)
    const int crow = b * 128 + hb * 64;    // EtT row base
    gemm_mainloop(smem,
                  g_B1T_hi + (size_t)m0 * Nn, g_B1T_lo + (size_t)m0 * Nn, Nn,
                  g_HT_hi + (size_t)crow * Nn, g_HT_lo + (size_t)crow * Nn, Nn,
                  Nn / KT, acc);

    const int tid = threadIdx.x, lane = tid & 31, wid = tid >> 5;
    const int wm = wid & 1, wn = wid >> 1;
    const int g = lane >> 2, tig = lane & 3;

    __syncthreads();                       // mainloop smem reads done
    float* Cs = (float*)smem;              // [64 e][65]
#pragma unroll
    for (int mi = 0; mi < 2; mi++) {
        const int mr = wm * 32 + mi * 16 + g;       // e-local
        const float s0 = g_L1[m0 + mr], s1 = g_L1[m0 + mr + 8];
#pragma unroll
        for (int ni = 0; ni < 4; ni++) {
            const int nc = wn * 32 + ni * 8 + 2 * tig;   // c-local
            Cs[mr * 65 + nc]           = acc[mi][ni][0] * s0;
            Cs[mr * 65 + nc + 1]       = acc[mi][ni][1] * s0;
            Cs[(mr + 8) * 65 + nc]     = acc[mi][ni][2] * s1;
            Cs[(mr + 8) * 65 + nc + 1] = acc[mi][ni][3] * s1;
        }
    }
    __syncthreads();
    // Each warp writes 16 output c-rows; lane covers e-chunk [2l, 2l+2).
#pragma unroll
    for (int rr = 0; rr < 16; rr++) {
        const int c = wid * 16 + rr;
        __nv_bfloat16 hb2[2], lb2[2];
        bf16_split(Cs[(2 * lane) * 65 + c],     hb2[0], lb2[0]);
        bf16_split(Cs[(2 * lane + 1) * 65 + c], hb2[1], lb2[1]);
        const size_t off = (size_t)(crow + c) * Ee + m0 + 2 * lane;
        *(uint32_t*)(g_EtT_hi + off) = *(const uint32_t*)hb2;
        *(uint32_t*)(g_EtT_lo + off) = *(const uint32_t*)lb2;
    }
}

// GEMM2 (K-split 4): dHp[sp][b][n][h] = sum_{e in split sp} B1[n,e]*EtT[b*128+h][e]
// Grid: x = n-tile (N/64), y = (b<<1)|hh, z = sp.
__global__ __launch_bounds__(128, 6) void gemm2_kernel() {
    extern __shared__ char smem[];
    float acc[2][4][4];
#pragma unroll
    for (int i = 0; i < 2; i++)
#pragma unroll
        for (int j = 0; j < 4; j++)
#pragma unroll
            for (int k = 0; k < 4; k++) acc[i][j][k] = 0.f;

    const int m0 = blockIdx.x * 64;        // n block
    const int b  = blockIdx.y >> 1;        // batch
    const int hh = blockIdx.y & 1;         // h half
    const int sp = blockIdx.z;             // K split
    const size_t ko = (size_t)sp * (Ee / 4);
    const int crow = b * 128 + hh * 64;
    gemm_mainloop(smem,
                  g_B1_hi + (size_t)m0 * Ee + ko, g_B1_lo + (size_t)m0 * Ee + ko, Ee,
                  g_EtT_hi + (size_t)crow * Ee + ko,
                  g_EtT_lo + (size_t)crow * Ee + ko, Ee,
                  (Ee / 4) / KT, acc);

    const int tid = threadIdx.x, lane = tid & 31, wid = tid >> 5;
    const int wm = wid & 1, wn = wid >> 1;
    const int g = lane >> 2, tig = lane & 3;
    float* outb = g_dH + (size_t)sp * (Bb * Nn * HH);
#pragma unroll
    for (int mi = 0; mi < 2; mi++) {
        const int gn = m0 + wm * 32 + mi * 16 + g;
        float* r0 = outb + ((size_t)b * Nn + gn) * HH;
        float* r1 = r0 + 8 * HH;
#pragma unroll
        for (int ni = 0; ni < 4; ni++) {
            const int h = hh * 64 + wn * 32 + ni * 8 + 2 * tig;
            *(float2*)(r0 + h) = make_float2(acc[mi][ni][0], acc[mi][ni][1]);
            *(float2*)(r1 + h) = make_float2(acc[mi][ni][2], acc[mi][ni][3]);
        }
    }
}

// ---------------------------------------------------------------------------
// Final: out = H + alpha * relu( (dHp0+dHp1+dHp2+dHp3) @ W^T )
// ---------------------------------------------------------------------------
__global__ __launch_bounds__(256) void final_kernel(
    const float* __restrict__ H, const float* __restrict__ W,
    const float* __restrict__ alpha_raw, float* __restrict__ out) {
    __shared__ float As[32][132];
    __shared__ float Ws[32][132];
    const int tid = threadIdx.x;
    const int tx = tid & 15, ty = tid >> 4;
    const int m0 = blockIdx.x * 128;
    const int r = tid >> 3, c4 = (tid & 7) * 4;
    const size_t DHP = (size_t)Bb * Nn * HH;

    float acc[8][8];
#pragma unroll
    for (int i = 0; i < 8; i++)
#pragma unroll
        for (int j = 0; j < 8; j++) acc[i][j] = 0.f;

    for (int h0 = 0; h0 < HH; h0 += 32) {
        __syncthreads();
#pragma unroll
        for (int p = 0; p < 4; p++) {
            const int row = r + p * 32;
            const size_t ai = (size_t)(m0 + row) * HH + h0 + c4;
            float4 a0 = *(const float4*)(g_dH + ai);
            float4 a1 = *(const float4*)(g_dH + DHP + ai);
            float4 a2 = *(const float4*)(g_dH + 2 * DHP + ai);
            float4 a3 = *(const float4*)(g_dH + 3 * DHP + ai);
            As[c4 + 0][row] = (a0.x + a1.x) + (a2.x + a3.x);
            As[c4 + 1][row] = (a0.y + a1.y) + (a2.y + a3.y);
            As[c4 + 2][row] = (a0.z + a1.z) + (a2.z + a3.z);
            As[c4 + 3][row] = (a0.w + a1.w) + (a2.w + a3.w);
            float4 wv = *(const float4*)(W + (size_t)row * HH + h0 + c4);
            Ws[c4 + 0][row] = wv.x; Ws[c4 + 1][row] = wv.y;
            Ws[c4 + 2][row] = wv.z; Ws[c4 + 3][row] = wv.w;
        }
        __syncthreads();
#pragma unroll
        for (int kk = 0; kk < 32; kk++) {
            float a[8], w[8];
            *(float4*)(a)     = *(const float4*)&As[kk][ty * 8];
            *(float4*)(a + 4) = *(const float4*)&As[kk][ty * 8 + 4];
            *(float4*)(w)     = *(const float4*)&Ws[kk][tx * 8];
            *(float4*)(w + 4) = *(const float4*)&Ws[kk][tx * 8 + 4];
#pragma unroll
            for (int i = 0; i < 8; i++)
#pragma unroll
                for (int j = 0; j < 8; j++)
                    acc[i][j] = fmaf(a[i], w[j], acc[i][j]);
        }
    }

    const float alpha = 0.05f / (1.0f + expf(-alpha_raw[0]));
#pragma unroll
    for (int i = 0; i < 8; i++) {
        const size_t m = (size_t)m0 + ty * 8 + i;
        const float* Hr = H + m * HH + tx * 8;
        float* Or = out + m * HH + tx * 8;
#pragma unroll
        for (int j = 0; j < 8; j++)
            Or[j] = Hr[j] + alpha * fmaxf(acc[i][j], 0.f);
    }
}

// ---------------------------------------------------------------------------
extern "C" void kernel_launch(void* const* d_in, const int* in_sizes, int n_in,
                              void* d_out, int out_size) {
    const float* H  = (const float*)d_in[0];
    const float* B1 = (const float*)d_in[1];
    const float* B2 = (const float*)d_in[2];
    const float* W  = (const float*)d_in[3];
    const float* ar = (const float*)d_in[4];
    float* out = (float*)d_out;

    cudaFuncSetAttribute(gemm1_kernel, cudaFuncAttributeMaxDynamicSharedMemorySize, SMEM_DYN);
    cudaFuncSetAttribute(gemm2_kernel, cudaFuncAttributeMaxDynamicSharedMemorySize, SMEM_DYN);

    // B1 [N,E] -> B1T hi/lo [E,N] + B1 hi/lo [N,E] + L1 partials (one read)
    tsplit_b1_kernel<<<dim3(Ee / 32, Nn / 32, 1), dim3(32, 8)>>>(B1);
    // H [b][n][h] -> HT hi/lo [b][h][n]
    tsplit_h_kernel<<<dim3(HH / 32, Nn / 32, Bb), dim3(32, 8)>>>(H);
    // L1[e] = sum partials + rowsum(B2^2)
    l1_finalize_kernel<<<Ee / 8, 256>>>(B2);

    // GEMM1 -> EtT hi/lo [CD][E] directly (fused transpose epilogue)
    gemm1_kernel<<<dim3(Ee / 64, Bb * 2), 128, SMEM_DYN>>>();
    // GEMM2 (K-split 4) -> dH partials
    gemm2_kernel<<<dim3(Nn / 64, Bb * 2, 4), 128, SMEM_DYN>>>();
    final_kernel<<<(Bb * Nn) / 128, 256>>>(H, W, ar, out);
}